// round 14
// baseline (speedup 1.0000x reference)
#include <cuda_runtime.h>
#include <cuda_fp16.h>
#include <math.h>

// ---------------------------------------------------------------------------
// 2-layer GAT forward, CSR-based, forked graph capture.  (R11 base)
//   side: init / hist(+slot) / scan_bsum / scan_out / scatter[0,Et/2)
//   main: gemm1 (+attn dots)  ...then... scatter[Et/2,Et)
//   join -> agg1 -> gemm2(+attn) -> agg2
// Flat softmax via __expf.  Agg: 2 edges/warp-iter via 16-lane groups.
// Scatter is atomic-free (slots from hist) and split across both streams to
// balance the fork arms (side CSR ~28us + half-scatter vs gemm1 ~30us + half).
// ---------------------------------------------------------------------------

#define NN 50000
#define EE 800000
#define ET (EE + NN)
#define NB ((NN + 1023) / 1024)

typedef unsigned long long ull;

// -------- scratch (device globals; no allocation allowed) -------------------
__device__ __half g_xp1h[NN * 128];
__device__ float  g_h   [NN * 128];
__device__ __half g_xp2h[NN * 64];
__device__ float2 g_as  [NN];
__device__ float2 g_ad  [NN];
__device__ int    g_deg[NN];
__device__ int    g_row[NN];
__device__ int    g_src[ET];
__device__ int    g_slot[ET];
__device__ int    g_bsum[NB];
__device__ int    g_is32 = 0;   // only ever set to 1 (idempotent across replays)

// -------- packed f32x2 helpers ----------------------------------------------
__device__ __forceinline__ ull pack2(float lo, float hi) {
    ull r; asm("mov.b64 %0, {%1, %2};" : "=l"(r) : "f"(lo), "f"(hi)); return r;
}
__device__ __forceinline__ void unpack2(ull v, float& lo, float& hi) {
    asm("mov.b64 {%0, %1}, %2;" : "=f"(lo), "=f"(hi) : "l"(v));
}
__device__ __forceinline__ ull fma2(ull a, ull b, ull c) {
    ull d; asm("fma.rn.f32x2 %0, %1, %2, %3;" : "=l"(d) : "l"(a), "l"(b), "l"(c));
    return d;
}

// -------- edge decode --------------------------------------------------------
__device__ __forceinline__ void load_edge(const void* ei, int E, int e,
                                          int& s, int& d) {
    if (e >= E) { s = d = e - E; return; }            // self loop
    if (g_is32) {
        const int* p = (const int*)ei;
        s = p[e]; d = p[E + e];
    } else {
        const long long* p = (const long long*)ei;
        s = (int)p[e]; d = (int)p[E + e];
    }
}

// -------- CSR build ----------------------------------------------------------
// int32 layout => odd 32-bit words are node ids (some nonzero);
// int64 layout => odd words are high halves of values < 2^31 => all zero.
__global__ void init_k(const unsigned* w, int n) {
    int i = blockIdx.x * blockDim.x + threadIdx.x;
    if (i < n) g_deg[i] = 0;
    if (i < 4096 && w[2 * i + 1] != 0u) g_is32 = 1;
}
// histogram + per-edge slot (atomicAdd return value)
__global__ void hist_k(const void* ei, int E, int n) {
    int e = blockIdx.x * blockDim.x + threadIdx.x;
    if (e >= E + n) return;
    int d;
    if (e >= E) d = e - E;
    else if (g_is32) d = ((const int*)ei)[E + e];
    else             d = (int)((const long long*)ei)[E + e];
    g_slot[e] = atomicAdd(&g_deg[d], 1);
}
__global__ void scan_bsum_k(int n) {
    __shared__ int wsum[8];
    int b = blockIdx.x, t = threadIdx.x;
    int base = b * 1024 + t * 4;
    int s = 0;
#pragma unroll
    for (int j = 0; j < 4; j++) {
        int i = base + j;
        if (i < n) s += g_deg[i];
    }
    int lane = t & 31, w = t >> 5;
#pragma unroll
    for (int o = 16; o; o >>= 1) s += __shfl_xor_sync(0xffffffffu, s, o);
    if (lane == 0) wsum[w] = s;
    __syncthreads();
    if (t == 0) {
        int tot = 0;
#pragma unroll
        for (int j = 0; j < 8; j++) tot += wsum[j];
        g_bsum[b] = tot;
    }
}
__global__ void scan_out_k(int n, int nb) {
    __shared__ int wsum[8], woff[8], blkoff;
    int b = blockIdx.x, t = threadIdx.x;
    int lane = t & 31, w = t >> 5;
    if (t < 64) {
        int v = (t < b && t < nb) ? g_bsum[t] : 0;
#pragma unroll
        for (int o = 16; o; o >>= 1) v += __shfl_xor_sync(0xffffffffu, v, o);
        if (lane == 0) wsum[w] = v;
    }
    __syncthreads();
    if (t == 0) blkoff = wsum[0] + wsum[1];
    __syncthreads();
    int base = b * 1024 + t * 4;
    int v[4];
#pragma unroll
    for (int j = 0; j < 4; j++) {
        int i = base + j;
        v[j] = (i < n) ? g_deg[i] : 0;
    }
    int s = v[0] + v[1] + v[2] + v[3];
    int inc = s;
#pragma unroll
    for (int o = 1; o < 32; o <<= 1) {
        int x = __shfl_up_sync(0xffffffffu, inc, o);
        if (lane >= o) inc += x;
    }
    if (lane == 31) wsum[w] = inc;
    __syncthreads();
    if (w == 0) {
        int x = (lane < 8) ? wsum[lane] : 0;
        int i8 = x;
#pragma unroll
        for (int o = 1; o < 8; o <<= 1) {
            int y = __shfl_up_sync(0xffffffffu, i8, o);
            if (lane >= o) i8 += y;
        }
        if (lane < 8) woff[lane] = i8 - x;
    }
    __syncthreads();
    int off = blkoff + woff[w] + (inc - s);
#pragma unroll
    for (int j = 0; j < 4; j++) {
        int i = base + j;
        if (i < n) g_row[i] = off;
        off += v[j];
    }
}
// atomic-free scatter over edge range [e0, e1)
__global__ void scatter_k(const void* ei, int E, int e0, int e1) {
    int e = e0 + blockIdx.x * blockDim.x + threadIdx.x;
    if (e >= e1) return;
    int s, d; load_edge(ei, E, e, s, d);
    g_src[g_row[d] + g_slot[e]] = s;
}

// -------- f32x2 GEMM + fused attn dots; fp16 output -------------------------
template <int C, int BM>
__global__ void gemm_attn_k(const float* __restrict__ X, const float* __restrict__ W,
                            __half* __restrict__ Yh, const float* __restrict__ As,
                            const float* __restrict__ Ad, int n) {
    constexpr int K = 128, BK = 16, TM = 8, TN = 4;
    constexpr int TCOLS = C / TN;
    constexpr int NT    = (BM / TM) * TCOLS;    // 256
    constexpr int GW    = (C / 2) / TN;
    __shared__ __align__(16) float Xs[BK][BM];
    __shared__ __align__(16) float Ws[BK][C];
    const int tid = threadIdx.x;
    const int tc = tid % TCOLS, tr = tid / TCOLS;
    const int row0 = blockIdx.x * BM;
    ull acc2[TM / 2][TN];
#pragma unroll
    for (int ip = 0; ip < TM / 2; ip++)
#pragma unroll
        for (int j = 0; j < TN; j++) acc2[ip][j] = pack2(0.f, 0.f);

    for (int kt = 0; kt < K; kt += BK) {
#pragma unroll
        for (int idx = tid; idx < BM * BK / 4; idx += NT) {
            int m = idx / (BK / 4), q = idx % (BK / 4);
            float4 v = make_float4(0.f, 0.f, 0.f, 0.f);
            if (row0 + m < n)
                v = *(const float4*)&X[(long long)(row0 + m) * K + kt + q * 4];
            Xs[q * 4 + 0][m] = v.x; Xs[q * 4 + 1][m] = v.y;
            Xs[q * 4 + 2][m] = v.z; Xs[q * 4 + 3][m] = v.w;
        }
#pragma unroll
        for (int idx = tid; idx < BK * C / 4; idx += NT) {
            int k = idx / (C / 4), q = idx % (C / 4);
            *(float4*)&Ws[k][q * 4] = *(const float4*)&W[(kt + k) * C + q * 4];
        }
        __syncthreads();
#pragma unroll
        for (int k = 0; k < BK; k++) {
            ull x2[TM / 2];
#pragma unroll
            for (int ip = 0; ip < TM / 2; ip++)
                x2[ip] = *(const ull*)&Xs[k][tr * TM + 2 * ip];
            float4 w = *(const float4*)&Ws[k][tc * TN];
            ull wd[TN] = {pack2(w.x, w.x), pack2(w.y, w.y),
                          pack2(w.z, w.z), pack2(w.w, w.w)};
#pragma unroll
            for (int ip = 0; ip < TM / 2; ip++)
#pragma unroll
                for (int j = 0; j < TN; j++)
                    acc2[ip][j] = fma2(x2[ip], wd[j], acc2[ip][j]);
        }
        __syncthreads();
    }
    float accf[TM][TN];
#pragma unroll
    for (int ip = 0; ip < TM / 2; ip++)
#pragma unroll
        for (int j = 0; j < TN; j++)
            unpack2(acc2[ip][j], accf[2 * ip][j], accf[2 * ip + 1][j]);
#pragma unroll
    for (int i = 0; i < TM; i++) {
        int r = row0 + tr * TM + i;
        if (r < n) {
            __half2 h0 = __floats2half2_rn(accf[i][0], accf[i][1]);
            __half2 h1 = __floats2half2_rn(accf[i][2], accf[i][3]);
            uint2 u; u.x = *(unsigned*)&h0; u.y = *(unsigned*)&h1;
            *(uint2*)&Yh[(long long)r * C + tc * TN] = u;
        }
    }
    float4 av = ((const float4*)As)[tc];
    float4 dv = ((const float4*)Ad)[tc];
    float sdot[TM], ddot[TM];
#pragma unroll
    for (int i = 0; i < TM; i++) {
        sdot[i] = accf[i][0] * av.x + accf[i][1] * av.y +
                  accf[i][2] * av.z + accf[i][3] * av.w;
        ddot[i] = accf[i][0] * dv.x + accf[i][1] * dv.y +
                  accf[i][2] * dv.z + accf[i][3] * dv.w;
#pragma unroll
        for (int o = GW / 2; o; o >>= 1) {
            sdot[i] += __shfl_xor_sync(0xffffffffu, sdot[i], o);
            ddot[i] += __shfl_xor_sync(0xffffffffu, ddot[i], o);
        }
    }
    if ((tc & (GW - 1)) == 0) {
        int h = (tc / GW) & 1;
#pragma unroll
        for (int i = 0; i < TM; i++) {
            int r = row0 + tr * TM + i;
            if (r < n) {
                ((float*)g_as)[r * 2 + h] = sdot[i];
                ((float*)g_ad)[r * 2 + h] = ddot[i];
            }
        }
    }
}

// ---- agg1: 2 edges/iteration, 16-lane groups, 8 ch/lane (uint4 gather) -----
__global__ void agg1_k(const __half* __restrict__ xph, const float* __restrict__ b1,
                       float* __restrict__ h, int n) {
    int g = blockIdx.x * blockDim.x + threadIdx.x;
    int node = g >> 5, lane = g & 31;
    if (node >= n) return;
    int sub = lane & 15, grp = lane >> 4;
    int start = g_row[node], deg = g_deg[node];
    float2 ad = g_ad[node];
    float acc[8];
#pragma unroll
    for (int i = 0; i < 8; i++) acc[i] = 0.f;
    float d0 = 0.f, d1 = 0.f;
    const uint4* xp = (const uint4*)xph;

    if (deg <= 32) {                       // fast path (~85% of nodes)
        int s = 0; float p0 = 0.f, p1 = 0.f;
        if (lane < deg) {
            s = g_src[start + lane];
            float2 as = g_as[s];
            float e0 = as.x + ad.x; e0 = e0 > 0.f ? e0 : 0.2f * e0;
            float e1 = as.y + ad.y; e1 = e1 > 0.f ? e1 : 0.2f * e1;
            p0 = __expf(e0); p1 = __expf(e1);
        }
        d0 = p0; d1 = p1;
        for (int j = 0; j < deg; j += 2) {
            int idx = j + grp;
            int   ss = __shfl_sync(0xffffffffu, s,  idx);
            float f0 = __shfl_sync(0xffffffffu, p0, idx);
            float f1 = __shfl_sync(0xffffffffu, p1, idx);
            float a  = (idx < deg) ? (sub < 8 ? f0 : f1) : 0.f;
            uint4 u = xp[ss * 16 + sub];
            float2 va = __half22float2(*(__half2*)&u.x);
            float2 vb = __half22float2(*(__half2*)&u.y);
            float2 vc = __half22float2(*(__half2*)&u.z);
            float2 vd = __half22float2(*(__half2*)&u.w);
            acc[0] = fmaf(va.x, a, acc[0]); acc[1] = fmaf(va.y, a, acc[1]);
            acc[2] = fmaf(vb.x, a, acc[2]); acc[3] = fmaf(vb.y, a, acc[3]);
            acc[4] = fmaf(vc.x, a, acc[4]); acc[5] = fmaf(vc.y, a, acc[5]);
            acc[6] = fmaf(vd.x, a, acc[6]); acc[7] = fmaf(vd.y, a, acc[7]);
        }
    } else {
        for (int base = 0; base < deg; base += 32) {
            int rem = deg - base; if (rem > 32) rem = 32;
            int s = 0; float p0 = 0.f, p1 = 0.f;
            if (lane < rem) {
                s = g_src[start + base + lane];
                float2 as = g_as[s];
                float e0 = as.x + ad.x; e0 = e0 > 0.f ? e0 : 0.2f * e0;
                float e1 = as.y + ad.y; e1 = e1 > 0.f ? e1 : 0.2f * e1;
                p0 = __expf(e0); p1 = __expf(e1);
            }
            d0 += p0; d1 += p1;
            for (int j = 0; j < rem; j += 2) {
                int idx = j + grp;
                int   ss = __shfl_sync(0xffffffffu, s,  idx & 31);
                float f0 = __shfl_sync(0xffffffffu, p0, idx & 31);
                float f1 = __shfl_sync(0xffffffffu, p1, idx & 31);
                float a  = (idx < rem) ? (sub < 8 ? f0 : f1) : 0.f;
                uint4 u = xp[ss * 16 + sub];
                float2 va = __half22float2(*(__half2*)&u.x);
                float2 vb = __half22float2(*(__half2*)&u.y);
                float2 vc = __half22float2(*(__half2*)&u.z);
                float2 vd = __half22float2(*(__half2*)&u.w);
                acc[0] = fmaf(va.x, a, acc[0]); acc[1] = fmaf(va.y, a, acc[1]);
                acc[2] = fmaf(vb.x, a, acc[2]); acc[3] = fmaf(vb.y, a, acc[3]);
                acc[4] = fmaf(vc.x, a, acc[4]); acc[5] = fmaf(vc.y, a, acc[5]);
                acc[6] = fmaf(vd.x, a, acc[6]); acc[7] = fmaf(vd.y, a, acc[7]);
            }
        }
    }
#pragma unroll
    for (int i = 0; i < 8; i++) acc[i] += __shfl_xor_sync(0xffffffffu, acc[i], 16);
#pragma unroll
    for (int o = 16; o; o >>= 1) {
        d0 += __shfl_xor_sync(0xffffffffu, d0, o);
        d1 += __shfl_xor_sync(0xffffffffu, d1, o);
    }
    if (lane < 16) {
        float r = 1.f / (sub < 8 ? d0 : d1);   // channels sub*8..+7: head0 iff sub<8
        float4 b0 = ((const float4*)b1)[sub * 2];
        float4 b1v = ((const float4*)b1)[sub * 2 + 1];
        float o0 = fmaf(acc[0], r, b0.x),  o1 = fmaf(acc[1], r, b0.y);
        float o2 = fmaf(acc[2], r, b0.z),  o3 = fmaf(acc[3], r, b0.w);
        float o4 = fmaf(acc[4], r, b1v.x), o5 = fmaf(acc[5], r, b1v.y);
        float o6 = fmaf(acc[6], r, b1v.z), o7 = fmaf(acc[7], r, b1v.w);
        o0 = o0 > 0.f ? o0 : expm1f(o0); o1 = o1 > 0.f ? o1 : expm1f(o1);
        o2 = o2 > 0.f ? o2 : expm1f(o2); o3 = o3 > 0.f ? o3 : expm1f(o3);
        o4 = o4 > 0.f ? o4 : expm1f(o4); o5 = o5 > 0.f ? o5 : expm1f(o5);
        o6 = o6 > 0.f ? o6 : expm1f(o6); o7 = o7 > 0.f ? o7 : expm1f(o7);
        ((float4*)h)[node * 32 + sub * 2]     = make_float4(o0, o1, o2, o3);
        ((float4*)h)[node * 32 + sub * 2 + 1] = make_float4(o4, o5, o6, o7);
    }
}

// ---- agg2: 2 edges/iteration, 16-lane groups, 4 ch/lane (uint2 gather) -----
__global__ void agg2_k(const __half* __restrict__ xph, const float* __restrict__ b2,
                       float* __restrict__ out, int n) {
    int g = blockIdx.x * blockDim.x + threadIdx.x;
    int node = g >> 5, lane = g & 31;
    if (node >= n) return;
    int sub = lane & 15, grp = lane >> 4;
    int start = g_row[node], deg = g_deg[node];
    float2 ad = g_ad[node];
    float acc[4];
#pragma unroll
    for (int i = 0; i < 4; i++) acc[i] = 0.f;
    float d0 = 0.f, d1 = 0.f;
    const uint2* xp = (const uint2*)xph;

    if (deg <= 32) {
        int s = 0; float p0 = 0.f, p1 = 0.f;
        if (lane < deg) {
            s = g_src[start + lane];
            float2 as = g_as[s];
            float e0 = as.x + ad.x; e0 = e0 > 0.f ? e0 : 0.2f * e0;
            float e1 = as.y + ad.y; e1 = e1 > 0.f ? e1 : 0.2f * e1;
            p0 = __expf(e0); p1 = __expf(e1);
        }
        d0 = p0; d1 = p1;
        for (int j = 0; j < deg; j += 2) {
            int idx = j + grp;
            int   ss = __shfl_sync(0xffffffffu, s,  idx);
            float f0 = __shfl_sync(0xffffffffu, p0, idx);
            float f1 = __shfl_sync(0xffffffffu, p1, idx);
            float a  = (idx < deg) ? (sub < 8 ? f0 : f1) : 0.f;
            uint2 u = xp[ss * 16 + sub];
            float2 va = __half22float2(*(__half2*)&u.x);
            float2 vb = __half22float2(*(__half2*)&u.y);
            acc[0] = fmaf(va.x, a, acc[0]); acc[1] = fmaf(va.y, a, acc[1]);
            acc[2] = fmaf(vb.x, a, acc[2]); acc[3] = fmaf(vb.y, a, acc[3]);
        }
    } else {
        for (int base = 0; base < deg; base += 32) {
            int rem = deg - base; if (rem > 32) rem = 32;
            int s = 0; float p0 = 0.f, p1 = 0.f;
            if (lane < rem) {
                s = g_src[start + base + lane];
                float2 as = g_as[s];
                float e0 = as.x + ad.x; e0 = e0 > 0.f ? e0 : 0.2f * e0;
                float e1 = as.y + ad.y; e1 = e1 > 0.f ? e1 : 0.2f * e1;
                p0 = __expf(e0); p1 = __expf(e1);
            }
            d0 += p0; d1 += p1;
            for (int j = 0; j < rem; j += 2) {
                int idx = j + grp;
                int   ss = __shfl_sync(0xffffffffu, s,  idx & 31);
                float f0 = __shfl_sync(0xffffffffu, p0, idx & 31);
                float f1 = __shfl_sync(0xffffffffu, p1, idx & 31);
                float a  = (idx < rem) ? (sub < 8 ? f0 : f1) : 0.f;
                uint2 u = xp[ss * 16 + sub];
                float2 va = __half22float2(*(__half2*)&u.x);
                float2 vb = __half22float2(*(__half2*)&u.y);
                acc[0] = fmaf(va.x, a, acc[0]); acc[1] = fmaf(va.y, a, acc[1]);
                acc[2] = fmaf(vb.x, a, acc[2]); acc[3] = fmaf(vb.y, a, acc[3]);
            }
        }
    }
#pragma unroll
    for (int i = 0; i < 4; i++) acc[i] += __shfl_xor_sync(0xffffffffu, acc[i], 16);
#pragma unroll
    for (int o = 16; o; o >>= 1) {
        d0 += __shfl_xor_sync(0xffffffffu, d0, o);
        d1 += __shfl_xor_sync(0xffffffffu, d1, o);
    }
    float r = 1.f / (sub < 8 ? d0 : d1);       // channels sub*4..+3: head0 iff sub<8
    float2 c0 = ((const float2*)b2)[sub * 2];
    float2 c1 = ((const float2*)b2)[sub * 2 + 1];
    float v0 = fmaf(acc[0], r, c0.x), v1 = fmaf(acc[1], r, c0.y);
    float v2 = fmaf(acc[2], r, c1.x), v3 = fmaf(acc[3], r, c1.y);
    float m = fmaxf(fmaxf(v0, v1), fmaxf(v2, v3));
#pragma unroll
    for (int o = 8; o; o >>= 1) m = fmaxf(m, __shfl_xor_sync(0xffffffffu, m, o));
    float sm = __expf(v0 - m) + __expf(v1 - m) + __expf(v2 - m) + __expf(v3 - m);
#pragma unroll
    for (int o = 8; o; o >>= 1) sm += __shfl_xor_sync(0xffffffffu, sm, o);
    float lse = m + __logf(sm);
    if (lane < 16)
        ((float4*)out)[node * 16 + sub] =
            make_float4(v0 - lse, v1 - lse, v2 - lse, v3 - lse);
}

// ---------------------------------------------------------------------------
extern "C" void kernel_launch(void* const* d_in, const int* in_sizes, int n_in,
                              void* d_out, int out_size) {
    const float* x   = (const float*)d_in[0];
    const void*  ei  = d_in[1];
    const float* W1  = (const float*)d_in[2];
    const float* a1s = (const float*)d_in[3];
    const float* a1d = (const float*)d_in[4];
    const float* b1  = (const float*)d_in[5];
    const float* W2  = (const float*)d_in[6];
    const float* a2s = (const float*)d_in[7];
    const float* a2d = (const float*)d_in[8];
    const float* b2  = (const float*)d_in[9];
    float* out = (float*)d_out;

    const int n  = in_sizes[0] / 128;          // 50000
    const int E  = in_sizes[1] / 2;            // 800000
    const int Et = E + n;
    const int nb = (n + 1023) / 1024;
    const int Eh = Et / 2;                     // scatter split point

    __half *xp1h, *xp2h; float* h;
    cudaGetSymbolAddress((void**)&xp1h, g_xp1h);
    cudaGetSymbolAddress((void**)&h,    g_h);
    cudaGetSymbolAddress((void**)&xp2h, g_xp2h);

    // one-time host-side resources (no device memory involved)
    static cudaStream_t s_csr = 0;
    static cudaEvent_t  ev_fork = 0, ev_join = 0, ev_scan = 0;
    if (s_csr == 0) {
        cudaStreamCreateWithFlags(&s_csr, cudaStreamNonBlocking);
        cudaEventCreateWithFlags(&ev_fork, cudaEventDisableTiming);
        cudaEventCreateWithFlags(&ev_join, cudaEventDisableTiming);
        cudaEventCreateWithFlags(&ev_scan, cudaEventDisableTiming);
    }

    const int B = 256;
    const int nwB = (n * 32 + B - 1) / B;

    bool fork = (s_csr != 0 && ev_fork != 0 && ev_join != 0 && ev_scan != 0);
    cudaStream_t sc = fork ? s_csr : 0;

    if (fork) {
        cudaEventRecord(ev_fork, 0);
        cudaStreamWaitEvent(sc, ev_fork, 0);
    }

    // ---- CSR build (side stream) ----
    init_k     <<<(n + B - 1) / B, B, 0, sc>>>((const unsigned*)ei, n);
    hist_k     <<<(Et + B - 1) / B, B, 0, sc>>>(ei, E, n);
    scan_bsum_k<<<nb, 256, 0, sc>>>(n);
    scan_out_k <<<nb, 256, 0, sc>>>(n, nb);
    if (fork) cudaEventRecord(ev_scan, sc);
    // first half of scatter stays on the side stream
    scatter_k  <<<(Eh + B - 1) / B, B, 0, sc>>>(ei, E, 0, Eh);

    // ---- layer-1 GEMM (+attn dots), concurrent with CSR build ----
    gemm_attn_k<128, 64><<<(n + 63) / 64, 256>>>(x, W1, xp1h, a1s, a1d, n);

    if (fork) {
        // second half of scatter on the main stream, after gemm1 + scan
        cudaStreamWaitEvent(0, ev_scan, 0);
        scatter_k<<<(Et - Eh + B - 1) / B, B>>>(ei, E, Eh, Et);
        cudaEventRecord(ev_join, sc);
        cudaStreamWaitEvent(0, ev_join, 0);
    } else {
        scatter_k<<<(Et - Eh + B - 1) / B, B>>>(ei, E, Eh, Et);
    }

    agg1_k<<<nwB, B>>>(xp1h, b1, h, n);

    // ---- layer 2 ----
    gemm_attn_k<64, 128><<<(n + 127) / 128, 256>>>(h, W2, xp2h, a2s, a2d, n);
    agg2_k<<<nwB, B>>>(xp2h, b2, out, n);
}

// round 15
// speedup vs baseline: 1.0342x; 1.0342x over previous
#include <cuda_runtime.h>
#include <cuda_fp16.h>
#include <math.h>

// ---------------------------------------------------------------------------
// 2-layer GAT forward, CSR-based, forked graph capture.  (R11 structure)
//   side: memset(g_deg) / detect / hist(+slot) / scan_bsum / scan_out / scatter
//   main: gemm1 (+attn dots) || CSR;  join;  agg1 -> gemm2(+attn) -> agg2
// Flat softmax via __expf.  Agg: 2 edges/warp-iter via 16-lane groups.
// Scatter atomic-free via hist's atomicAdd-returned slots.
// ---------------------------------------------------------------------------

#define NN 50000
#define EE 800000
#define ET (EE + NN)
#define NB ((NN + 1023) / 1024)

typedef unsigned long long ull;

// -------- scratch (device globals; no allocation allowed) -------------------
__device__ __half g_xp1h[NN * 128];
__device__ float  g_h   [NN * 128];
__device__ __half g_xp2h[NN * 64];
__device__ float2 g_as  [NN];
__device__ float2 g_ad  [NN];
__device__ int    g_deg[NN];
__device__ int    g_row[NN];
__device__ int    g_src[ET];
__device__ int    g_slot[ET];
__device__ int    g_bsum[NB];
__device__ int    g_is32 = 0;   // only ever set to 1 (idempotent across replays)

// -------- packed f32x2 helpers ----------------------------------------------
__device__ __forceinline__ ull pack2(float lo, float hi) {
    ull r; asm("mov.b64 %0, {%1, %2};" : "=l"(r) : "f"(lo), "f"(hi)); return r;
}
__device__ __forceinline__ void unpack2(ull v, float& lo, float& hi) {
    asm("mov.b64 {%0, %1}, %2;" : "=f"(lo), "=f"(hi) : "l"(v));
}
__device__ __forceinline__ ull fma2(ull a, ull b, ull c) {
    ull d; asm("fma.rn.f32x2 %0, %1, %2, %3;" : "=l"(d) : "l"(a), "l"(b), "l"(c));
    return d;
}

// -------- edge decode --------------------------------------------------------
__device__ __forceinline__ void load_edge(const void* ei, int E, int e,
                                          int& s, int& d) {
    if (e >= E) { s = d = e - E; return; }            // self loop
    if (g_is32) {
        const int* p = (const int*)ei;
        s = p[e]; d = p[E + e];
    } else {
        const long long* p = (const long long*)ei;
        s = (int)p[e]; d = (int)p[E + e];
    }
}

// -------- CSR build ----------------------------------------------------------
// int32 layout => odd 32-bit words are node ids (some nonzero);
// int64 layout => odd words are high halves of values < 2^31 => all zero.
__global__ void detect_k(const unsigned* w) {
    int i = blockIdx.x * blockDim.x + threadIdx.x;
    if (i < 4096 && w[2 * i + 1] != 0u) g_is32 = 1;
}
// histogram + per-edge slot (atomicAdd return value); g_deg pre-zeroed by memset
__global__ void hist_k(const void* ei, int E, int n) {
    int e = blockIdx.x * blockDim.x + threadIdx.x;
    if (e >= E + n) return;
    int d;
    if (e >= E) d = e - E;
    else if (g_is32) d = ((const int*)ei)[E + e];
    else             d = (int)((const long long*)ei)[E + e];
    g_slot[e] = atomicAdd(&g_deg[d], 1);
}
__global__ void scan_bsum_k(int n) {
    __shared__ int wsum[8];
    int b = blockIdx.x, t = threadIdx.x;
    int base = b * 1024 + t * 4;
    int s = 0;
#pragma unroll
    for (int j = 0; j < 4; j++) {
        int i = base + j;
        if (i < n) s += g_deg[i];
    }
    int lane = t & 31, w = t >> 5;
#pragma unroll
    for (int o = 16; o; o >>= 1) s += __shfl_xor_sync(0xffffffffu, s, o);
    if (lane == 0) wsum[w] = s;
    __syncthreads();
    if (t == 0) {
        int tot = 0;
#pragma unroll
        for (int j = 0; j < 8; j++) tot += wsum[j];
        g_bsum[b] = tot;
    }
}
__global__ void scan_out_k(int n, int nb) {
    __shared__ int wsum[8], woff[8], blkoff;
    int b = blockIdx.x, t = threadIdx.x;
    int lane = t & 31, w = t >> 5;
    if (t < 64) {
        int v = (t < b && t < nb) ? g_bsum[t] : 0;
#pragma unroll
        for (int o = 16; o; o >>= 1) v += __shfl_xor_sync(0xffffffffu, v, o);
        if (lane == 0) wsum[w] = v;
    }
    __syncthreads();
    if (t == 0) blkoff = wsum[0] + wsum[1];
    __syncthreads();
    int base = b * 1024 + t * 4;
    int v[4];
#pragma unroll
    for (int j = 0; j < 4; j++) {
        int i = base + j;
        v[j] = (i < n) ? g_deg[i] : 0;
    }
    int s = v[0] + v[1] + v[2] + v[3];
    int inc = s;
#pragma unroll
    for (int o = 1; o < 32; o <<= 1) {
        int x = __shfl_up_sync(0xffffffffu, inc, o);
        if (lane >= o) inc += x;
    }
    if (lane == 31) wsum[w] = inc;
    __syncthreads();
    if (w == 0) {
        int x = (lane < 8) ? wsum[lane] : 0;
        int i8 = x;
#pragma unroll
        for (int o = 1; o < 8; o <<= 1) {
            int y = __shfl_up_sync(0xffffffffu, i8, o);
            if (lane >= o) i8 += y;
        }
        if (lane < 8) woff[lane] = i8 - x;
    }
    __syncthreads();
    int off = blkoff + woff[w] + (inc - s);
#pragma unroll
    for (int j = 0; j < 4; j++) {
        int i = base + j;
        if (i < n) g_row[i] = off;
        off += v[j];
    }
}
// atomic-free scatter: slot precomputed in hist
__global__ void scatter_k(const void* ei, int E, int n) {
    int e = blockIdx.x * blockDim.x + threadIdx.x;
    if (e >= E + n) return;
    int s, d; load_edge(ei, E, e, s, d);
    g_src[g_row[d] + g_slot[e]] = s;
}

// -------- f32x2 GEMM + fused attn dots; fp16 output -------------------------
template <int C, int BM>
__global__ void gemm_attn_k(const float* __restrict__ X, const float* __restrict__ W,
                            __half* __restrict__ Yh, const float* __restrict__ As,
                            const float* __restrict__ Ad, int n) {
    constexpr int K = 128, BK = 16, TM = 8, TN = 4;
    constexpr int TCOLS = C / TN;
    constexpr int NT    = (BM / TM) * TCOLS;    // 256
    constexpr int GW    = (C / 2) / TN;
    __shared__ __align__(16) float Xs[BK][BM];
    __shared__ __align__(16) float Ws[BK][C];
    const int tid = threadIdx.x;
    const int tc = tid % TCOLS, tr = tid / TCOLS;
    const int row0 = blockIdx.x * BM;
    ull acc2[TM / 2][TN];
#pragma unroll
    for (int ip = 0; ip < TM / 2; ip++)
#pragma unroll
        for (int j = 0; j < TN; j++) acc2[ip][j] = pack2(0.f, 0.f);

    for (int kt = 0; kt < K; kt += BK) {
#pragma unroll
        for (int idx = tid; idx < BM * BK / 4; idx += NT) {
            int m = idx / (BK / 4), q = idx % (BK / 4);
            float4 v = make_float4(0.f, 0.f, 0.f, 0.f);
            if (row0 + m < n)
                v = *(const float4*)&X[(long long)(row0 + m) * K + kt + q * 4];
            Xs[q * 4 + 0][m] = v.x; Xs[q * 4 + 1][m] = v.y;
            Xs[q * 4 + 2][m] = v.z; Xs[q * 4 + 3][m] = v.w;
        }
#pragma unroll
        for (int idx = tid; idx < BK * C / 4; idx += NT) {
            int k = idx / (C / 4), q = idx % (C / 4);
            *(float4*)&Ws[k][q * 4] = *(const float4*)&W[(kt + k) * C + q * 4];
        }
        __syncthreads();
#pragma unroll
        for (int k = 0; k < BK; k++) {
            ull x2[TM / 2];
#pragma unroll
            for (int ip = 0; ip < TM / 2; ip++)
                x2[ip] = *(const ull*)&Xs[k][tr * TM + 2 * ip];
            float4 w = *(const float4*)&Ws[k][tc * TN];
            ull wd[TN] = {pack2(w.x, w.x), pack2(w.y, w.y),
                          pack2(w.z, w.z), pack2(w.w, w.w)};
#pragma unroll
            for (int ip = 0; ip < TM / 2; ip++)
#pragma unroll
                for (int j = 0; j < TN; j++)
                    acc2[ip][j] = fma2(x2[ip], wd[j], acc2[ip][j]);
        }
        __syncthreads();
    }
    float accf[TM][TN];
#pragma unroll
    for (int ip = 0; ip < TM / 2; ip++)
#pragma unroll
        for (int j = 0; j < TN; j++)
            unpack2(acc2[ip][j], accf[2 * ip][j], accf[2 * ip + 1][j]);
#pragma unroll
    for (int i = 0; i < TM; i++) {
        int r = row0 + tr * TM + i;
        if (r < n) {
            __half2 h0 = __floats2half2_rn(accf[i][0], accf[i][1]);
            __half2 h1 = __floats2half2_rn(accf[i][2], accf[i][3]);
            uint2 u; u.x = *(unsigned*)&h0; u.y = *(unsigned*)&h1;
            *(uint2*)&Yh[(long long)r * C + tc * TN] = u;
        }
    }
    float4 av = ((const float4*)As)[tc];
    float4 dv = ((const float4*)Ad)[tc];
    float sdot[TM], ddot[TM];
#pragma unroll
    for (int i = 0; i < TM; i++) {
        sdot[i] = accf[i][0] * av.x + accf[i][1] * av.y +
                  accf[i][2] * av.z + accf[i][3] * av.w;
        ddot[i] = accf[i][0] * dv.x + accf[i][1] * dv.y +
                  accf[i][2] * dv.z + accf[i][3] * dv.w;
#pragma unroll
        for (int o = GW / 2; o; o >>= 1) {
            sdot[i] += __shfl_xor_sync(0xffffffffu, sdot[i], o);
            ddot[i] += __shfl_xor_sync(0xffffffffu, ddot[i], o);
        }
    }
    if ((tc & (GW - 1)) == 0) {
        int h = (tc / GW) & 1;
#pragma unroll
        for (int i = 0; i < TM; i++) {
            int r = row0 + tr * TM + i;
            if (r < n) {
                ((float*)g_as)[r * 2 + h] = sdot[i];
                ((float*)g_ad)[r * 2 + h] = ddot[i];
            }
        }
    }
}

// ---- agg1: 2 edges/iteration, 16-lane groups, 8 ch/lane (uint4 gather) -----
__global__ void agg1_k(const __half* __restrict__ xph, const float* __restrict__ b1,
                       float* __restrict__ h, int n) {
    int g = blockIdx.x * blockDim.x + threadIdx.x;
    int node = g >> 5, lane = g & 31;
    if (node >= n) return;
    int sub = lane & 15, grp = lane >> 4;
    int start = g_row[node], deg = g_deg[node];
    float2 ad = g_ad[node];
    float acc[8];
#pragma unroll
    for (int i = 0; i < 8; i++) acc[i] = 0.f;
    float d0 = 0.f, d1 = 0.f;
    const uint4* xp = (const uint4*)xph;

    if (deg <= 32) {                       // fast path (~85% of nodes)
        int s = 0; float p0 = 0.f, p1 = 0.f;
        if (lane < deg) {
            s = g_src[start + lane];
            float2 as = g_as[s];
            float e0 = as.x + ad.x; e0 = e0 > 0.f ? e0 : 0.2f * e0;
            float e1 = as.y + ad.y; e1 = e1 > 0.f ? e1 : 0.2f * e1;
            p0 = __expf(e0); p1 = __expf(e1);
        }
        d0 = p0; d1 = p1;
        for (int j = 0; j < deg; j += 2) {
            int idx = j + grp;
            int   ss = __shfl_sync(0xffffffffu, s,  idx);
            float f0 = __shfl_sync(0xffffffffu, p0, idx);
            float f1 = __shfl_sync(0xffffffffu, p1, idx);
            float a  = (idx < deg) ? (sub < 8 ? f0 : f1) : 0.f;
            uint4 u = xp[ss * 16 + sub];
            float2 va = __half22float2(*(__half2*)&u.x);
            float2 vb = __half22float2(*(__half2*)&u.y);
            float2 vc = __half22float2(*(__half2*)&u.z);
            float2 vd = __half22float2(*(__half2*)&u.w);
            acc[0] = fmaf(va.x, a, acc[0]); acc[1] = fmaf(va.y, a, acc[1]);
            acc[2] = fmaf(vb.x, a, acc[2]); acc[3] = fmaf(vb.y, a, acc[3]);
            acc[4] = fmaf(vc.x, a, acc[4]); acc[5] = fmaf(vc.y, a, acc[5]);
            acc[6] = fmaf(vd.x, a, acc[6]); acc[7] = fmaf(vd.y, a, acc[7]);
        }
    } else {
        for (int base = 0; base < deg; base += 32) {
            int rem = deg - base; if (rem > 32) rem = 32;
            int s = 0; float p0 = 0.f, p1 = 0.f;
            if (lane < rem) {
                s = g_src[start + base + lane];
                float2 as = g_as[s];
                float e0 = as.x + ad.x; e0 = e0 > 0.f ? e0 : 0.2f * e0;
                float e1 = as.y + ad.y; e1 = e1 > 0.f ? e1 : 0.2f * e1;
                p0 = __expf(e0); p1 = __expf(e1);
            }
            d0 += p0; d1 += p1;
            for (int j = 0; j < rem; j += 2) {
                int idx = j + grp;
                int   ss = __shfl_sync(0xffffffffu, s,  idx & 31);
                float f0 = __shfl_sync(0xffffffffu, p0, idx & 31);
                float f1 = __shfl_sync(0xffffffffu, p1, idx & 31);
                float a  = (idx < rem) ? (sub < 8 ? f0 : f1) : 0.f;
                uint4 u = xp[ss * 16 + sub];
                float2 va = __half22float2(*(__half2*)&u.x);
                float2 vb = __half22float2(*(__half2*)&u.y);
                float2 vc = __half22float2(*(__half2*)&u.z);
                float2 vd = __half22float2(*(__half2*)&u.w);
                acc[0] = fmaf(va.x, a, acc[0]); acc[1] = fmaf(va.y, a, acc[1]);
                acc[2] = fmaf(vb.x, a, acc[2]); acc[3] = fmaf(vb.y, a, acc[3]);
                acc[4] = fmaf(vc.x, a, acc[4]); acc[5] = fmaf(vc.y, a, acc[5]);
                acc[6] = fmaf(vd.x, a, acc[6]); acc[7] = fmaf(vd.y, a, acc[7]);
            }
        }
    }
#pragma unroll
    for (int i = 0; i < 8; i++) acc[i] += __shfl_xor_sync(0xffffffffu, acc[i], 16);
#pragma unroll
    for (int o = 16; o; o >>= 1) {
        d0 += __shfl_xor_sync(0xffffffffu, d0, o);
        d1 += __shfl_xor_sync(0xffffffffu, d1, o);
    }
    if (lane < 16) {
        float r = 1.f / (sub < 8 ? d0 : d1);   // channels sub*8..+7: head0 iff sub<8
        float4 b0 = ((const float4*)b1)[sub * 2];
        float4 b1v = ((const float4*)b1)[sub * 2 + 1];
        float o0 = fmaf(acc[0], r, b0.x),  o1 = fmaf(acc[1], r, b0.y);
        float o2 = fmaf(acc[2], r, b0.z),  o3 = fmaf(acc[3], r, b0.w);
        float o4 = fmaf(acc[4], r, b1v.x), o5 = fmaf(acc[5], r, b1v.y);
        float o6 = fmaf(acc[6], r, b1v.z), o7 = fmaf(acc[7], r, b1v.w);
        o0 = o0 > 0.f ? o0 : expm1f(o0); o1 = o1 > 0.f ? o1 : expm1f(o1);
        o2 = o2 > 0.f ? o2 : expm1f(o2); o3 = o3 > 0.f ? o3 : expm1f(o3);
        o4 = o4 > 0.f ? o4 : expm1f(o4); o5 = o5 > 0.f ? o5 : expm1f(o5);
        o6 = o6 > 0.f ? o6 : expm1f(o6); o7 = o7 > 0.f ? o7 : expm1f(o7);
        ((float4*)h)[node * 32 + sub * 2]     = make_float4(o0, o1, o2, o3);
        ((float4*)h)[node * 32 + sub * 2 + 1] = make_float4(o4, o5, o6, o7);
    }
}

// ---- agg2: 2 edges/iteration, 16-lane groups, 4 ch/lane (uint2 gather) -----
__global__ void agg2_k(const __half* __restrict__ xph, const float* __restrict__ b2,
                       float* __restrict__ out, int n) {
    int g = blockIdx.x * blockDim.x + threadIdx.x;
    int node = g >> 5, lane = g & 31;
    if (node >= n) return;
    int sub = lane & 15, grp = lane >> 4;
    int start = g_row[node], deg = g_deg[node];
    float2 ad = g_ad[node];
    float acc[4];
#pragma unroll
    for (int i = 0; i < 4; i++) acc[i] = 0.f;
    float d0 = 0.f, d1 = 0.f;
    const uint2* xp = (const uint2*)xph;

    if (deg <= 32) {
        int s = 0; float p0 = 0.f, p1 = 0.f;
        if (lane < deg) {
            s = g_src[start + lane];
            float2 as = g_as[s];
            float e0 = as.x + ad.x; e0 = e0 > 0.f ? e0 : 0.2f * e0;
            float e1 = as.y + ad.y; e1 = e1 > 0.f ? e1 : 0.2f * e1;
            p0 = __expf(e0); p1 = __expf(e1);
        }
        d0 = p0; d1 = p1;
        for (int j = 0; j < deg; j += 2) {
            int idx = j + grp;
            int   ss = __shfl_sync(0xffffffffu, s,  idx);
            float f0 = __shfl_sync(0xffffffffu, p0, idx);
            float f1 = __shfl_sync(0xffffffffu, p1, idx);
            float a  = (idx < deg) ? (sub < 8 ? f0 : f1) : 0.f;
            uint2 u = xp[ss * 16 + sub];
            float2 va = __half22float2(*(__half2*)&u.x);
            float2 vb = __half22float2(*(__half2*)&u.y);
            acc[0] = fmaf(va.x, a, acc[0]); acc[1] = fmaf(va.y, a, acc[1]);
            acc[2] = fmaf(vb.x, a, acc[2]); acc[3] = fmaf(vb.y, a, acc[3]);
        }
    } else {
        for (int base = 0; base < deg; base += 32) {
            int rem = deg - base; if (rem > 32) rem = 32;
            int s = 0; float p0 = 0.f, p1 = 0.f;
            if (lane < rem) {
                s = g_src[start + base + lane];
                float2 as = g_as[s];
                float e0 = as.x + ad.x; e0 = e0 > 0.f ? e0 : 0.2f * e0;
                float e1 = as.y + ad.y; e1 = e1 > 0.f ? e1 : 0.2f * e1;
                p0 = __expf(e0); p1 = __expf(e1);
            }
            d0 += p0; d1 += p1;
            for (int j = 0; j < rem; j += 2) {
                int idx = j + grp;
                int   ss = __shfl_sync(0xffffffffu, s,  idx & 31);
                float f0 = __shfl_sync(0xffffffffu, p0, idx & 31);
                float f1 = __shfl_sync(0xffffffffu, p1, idx & 31);
                float a  = (idx < rem) ? (sub < 8 ? f0 : f1) : 0.f;
                uint2 u = xp[ss * 16 + sub];
                float2 va = __half22float2(*(__half2*)&u.x);
                float2 vb = __half22float2(*(__half2*)&u.y);
                acc[0] = fmaf(va.x, a, acc[0]); acc[1] = fmaf(va.y, a, acc[1]);
                acc[2] = fmaf(vb.x, a, acc[2]); acc[3] = fmaf(vb.y, a, acc[3]);
            }
        }
    }
#pragma unroll
    for (int i = 0; i < 4; i++) acc[i] += __shfl_xor_sync(0xffffffffu, acc[i], 16);
#pragma unroll
    for (int o = 16; o; o >>= 1) {
        d0 += __shfl_xor_sync(0xffffffffu, d0, o);
        d1 += __shfl_xor_sync(0xffffffffu, d1, o);
    }
    float r = 1.f / (sub < 8 ? d0 : d1);       // channels sub*4..+3: head0 iff sub<8
    float2 c0 = ((const float2*)b2)[sub * 2];
    float2 c1 = ((const float2*)b2)[sub * 2 + 1];
    float v0 = fmaf(acc[0], r, c0.x), v1 = fmaf(acc[1], r, c0.y);
    float v2 = fmaf(acc[2], r, c1.x), v3 = fmaf(acc[3], r, c1.y);
    // log_softmax over 64 channels: both 16-lane groups hold identical folded
    // values, so reduce within the 16-lane group only (offsets 8,4,2,1).
    float m = fmaxf(fmaxf(v0, v1), fmaxf(v2, v3));
#pragma unroll
    for (int o = 8; o; o >>= 1) m = fmaxf(m, __shfl_xor_sync(0xffffffffu, m, o));
    float sm = __expf(v0 - m) + __expf(v1 - m) + __expf(v2 - m) + __expf(v3 - m);
#pragma unroll
    for (int o = 8; o; o >>= 1) sm += __shfl_xor_sync(0xffffffffu, sm, o);
    float lse = m + __logf(sm);
    if (lane < 16)
        ((float4*)out)[node * 16 + sub] =
            make_float4(v0 - lse, v1 - lse, v2 - lse, v3 - lse);
}

// ---------------------------------------------------------------------------
extern "C" void kernel_launch(void* const* d_in, const int* in_sizes, int n_in,
                              void* d_out, int out_size) {
    const float* x   = (const float*)d_in[0];
    const void*  ei  = d_in[1];
    const float* W1  = (const float*)d_in[2];
    const float* a1s = (const float*)d_in[3];
    const float* a1d = (const float*)d_in[4];
    const float* b1  = (const float*)d_in[5];
    const float* W2  = (const float*)d_in[6];
    const float* a2s = (const float*)d_in[7];
    const float* a2d = (const float*)d_in[8];
    const float* b2  = (const float*)d_in[9];
    float* out = (float*)d_out;

    const int n  = in_sizes[0] / 128;          // 50000
    const int E  = in_sizes[1] / 2;            // 800000
    const int Et = E + n;
    const int nb = (n + 1023) / 1024;

    __half *xp1h, *xp2h; float *h; int *degp;
    cudaGetSymbolAddress((void**)&xp1h, g_xp1h);
    cudaGetSymbolAddress((void**)&h,    g_h);
    cudaGetSymbolAddress((void**)&xp2h, g_xp2h);
    cudaGetSymbolAddress((void**)&degp, g_deg);

    // one-time host-side resources (no device memory involved)
    static cudaStream_t s_csr = 0;
    static cudaEvent_t  ev_fork = 0, ev_join = 0;
    if (s_csr == 0) {
        cudaStreamCreateWithFlags(&s_csr, cudaStreamNonBlocking);
        cudaEventCreateWithFlags(&ev_fork, cudaEventDisableTiming);
        cudaEventCreateWithFlags(&ev_join, cudaEventDisableTiming);
    }

    const int B = 256;
    const int nwB = (n * 32 + B - 1) / B;

    bool fork = (s_csr != 0 && ev_fork != 0 && ev_join != 0);
    cudaStream_t sc = fork ? s_csr : 0;

    if (fork) {
        cudaEventRecord(ev_fork, 0);
        cudaStreamWaitEvent(sc, ev_fork, 0);
    }

    // ---- CSR build (side stream) ----
    cudaMemsetAsync(degp, 0, n * sizeof(int), sc);   // zero g_deg (memset node)
    detect_k   <<<16, 256, 0, sc>>>((const unsigned*)ei);
    hist_k     <<<(Et + B - 1) / B, B, 0, sc>>>(ei, E, n);
    scan_bsum_k<<<nb, 256, 0, sc>>>(n);
    scan_out_k <<<nb, 256, 0, sc>>>(n, nb);
    scatter_k  <<<(Et + B - 1) / B, B, 0, sc>>>(ei, E, n);

    // ---- layer-1 GEMM (+attn dots), concurrent with CSR build ----
    gemm_attn_k<128, 64><<<(n + 63) / 64, 256>>>(x, W1, xp1h, a1s, a1d, n);

    if (fork) {
        cudaEventRecord(ev_join, sc);
        cudaStreamWaitEvent(0, ev_join, 0);
    }

    agg1_k<<<nwB, B>>>(xp1h, b1, h, n);

    // ---- layer 2 ----
    gemm_attn_k<64, 128><<<(n + 127) / 128, 256>>>(h, W2, xp2h, a2s, a2d, n);
    agg2_k<<<nwB, B>>>(xp2h, b2, out, n);
}

// round 16
// speedup vs baseline: 1.0376x; 1.0033x over previous
#include <cuda_runtime.h>
#include <cuda_fp16.h>
#include <math.h>

// ---------------------------------------------------------------------------
// 2-layer GAT forward, CSR-based, forked graph capture.
//   main: detect -> [fork] gemm1 (+attn dots)
//   side: memset(g_deg) / hist(+slot) / fused scan / scatter
//   join -> agg1 -> gemm2(+attn) -> agg2
// Flat softmax via __expf.  Agg: 2 edges/warp-iter via 16-lane groups.
// Scatter atomic-free via hist's atomicAdd-returned slots.
// ---------------------------------------------------------------------------

#define NN 50000
#define EE 800000
#define ET (EE + NN)
#define NB ((NN + 1023) / 1024)

typedef unsigned long long ull;

// -------- scratch (device globals; no allocation allowed) -------------------
__device__ __half g_xp1h[NN * 128];
__device__ float  g_h   [NN * 128];
__device__ __half g_xp2h[NN * 64];
__device__ float2 g_as  [NN];
__device__ float2 g_ad  [NN];
__device__ int    g_deg[NN];
__device__ int    g_row[NN];
__device__ int    g_src[ET];
__device__ int    g_slot[ET];
__device__ int    g_is32 = 0;   // only ever set to 1 (idempotent across replays)

// -------- packed f32x2 helpers ----------------------------------------------
__device__ __forceinline__ ull pack2(float lo, float hi) {
    ull r; asm("mov.b64 %0, {%1, %2};" : "=l"(r) : "f"(lo), "f"(hi)); return r;
}
__device__ __forceinline__ void unpack2(ull v, float& lo, float& hi) {
    asm("mov.b64 {%0, %1}, %2;" : "=f"(lo), "=f"(hi) : "l"(v));
}
__device__ __forceinline__ ull fma2(ull a, ull b, ull c) {
    ull d; asm("fma.rn.f32x2 %0, %1, %2, %3;" : "=l"(d) : "l"(a), "l"(b), "l"(c));
    return d;
}

// -------- edge decode --------------------------------------------------------
__device__ __forceinline__ void load_edge(const void* ei, int E, int e,
                                          int& s, int& d) {
    if (e >= E) { s = d = e - E; return; }            // self loop
    if (g_is32) {
        const int* p = (const int*)ei;
        s = p[e]; d = p[E + e];
    } else {
        const long long* p = (const long long*)ei;
        s = (int)p[e]; d = (int)p[E + e];
    }
}

// -------- CSR build ----------------------------------------------------------
// int32 layout => odd 32-bit words are node ids (some nonzero);
// int64 layout => odd words are high halves of values < 2^31 => all zero.
__global__ void detect_k(const unsigned* w) {
    int i = blockIdx.x * blockDim.x + threadIdx.x;
    if (i < 4096 && w[2 * i + 1] != 0u) g_is32 = 1;
}
// histogram + per-edge slot (atomicAdd return value); g_deg pre-zeroed by memset
__global__ void hist_k(const void* ei, int E, int n) {
    int e = blockIdx.x * blockDim.x + threadIdx.x;
    if (e >= E + n) return;
    int d;
    if (e >= E) d = e - E;
    else if (g_is32) d = ((const int*)ei)[E + e];
    else             d = (int)((const long long*)ei)[E + e];
    g_slot[e] = atomicAdd(&g_deg[d], 1);
}
// fused device-wide exclusive scan of g_deg -> g_row.
// Each block (1024 nodes) computes its offset by directly summing all g_deg
// entries before its range (<=1.2M redundant L2-resident reads total).
__global__ void scan_k(int n) {
    __shared__ int wsum[8], woff[8], blkoff_s;
    int b = blockIdx.x, t = threadIdx.x;
    int lane = t & 31, w = t >> 5;
    // block offset = sum g_deg[0 .. b*1024)
    int pre = 0;
    for (int i = t; i < b * 1024; i += 256) pre += g_deg[i];
#pragma unroll
    for (int o = 16; o; o >>= 1) pre += __shfl_xor_sync(0xffffffffu, pre, o);
    if (lane == 0) wsum[w] = pre;
    __syncthreads();
    if (t == 0) {
        int tot = 0;
#pragma unroll
        for (int j = 0; j < 8; j++) tot += wsum[j];
        blkoff_s = tot;
    }
    __syncthreads();
    int blkoff = blkoff_s;
    // local exclusive scan of this block's 1024 entries (4 per thread)
    int base = b * 1024 + t * 4;
    int v[4];
#pragma unroll
    for (int j = 0; j < 4; j++) {
        int i = base + j;
        v[j] = (i < n) ? g_deg[i] : 0;
    }
    int s = v[0] + v[1] + v[2] + v[3];
    int inc = s;
#pragma unroll
    for (int o = 1; o < 32; o <<= 1) {
        int x = __shfl_up_sync(0xffffffffu, inc, o);
        if (lane >= o) inc += x;
    }
    if (lane == 31) wsum[w] = inc;
    __syncthreads();
    if (w == 0) {
        int x = (lane < 8) ? wsum[lane] : 0;
        int i8 = x;
#pragma unroll
        for (int o = 1; o < 8; o <<= 1) {
            int y = __shfl_up_sync(0xffffffffu, i8, o);
            if (lane >= o) i8 += y;
        }
        if (lane < 8) woff[lane] = i8 - x;
    }
    __syncthreads();
    int off = blkoff + woff[w] + (inc - s);
#pragma unroll
    for (int j = 0; j < 4; j++) {
        int i = base + j;
        if (i < n) g_row[i] = off;
        off += v[j];
    }
}
// atomic-free scatter: slot precomputed in hist
__global__ void scatter_k(const void* ei, int E, int n) {
    int e = blockIdx.x * blockDim.x + threadIdx.x;
    if (e >= E + n) return;
    int s, d; load_edge(ei, E, e, s, d);
    g_src[g_row[d] + g_slot[e]] = s;
}

// -------- f32x2 GEMM + fused attn dots; fp16 output -------------------------
template <int C, int BM>
__global__ void gemm_attn_k(const float* __restrict__ X, const float* __restrict__ W,
                            __half* __restrict__ Yh, const float* __restrict__ As,
                            const float* __restrict__ Ad, int n) {
    constexpr int K = 128, BK = 16, TM = 8, TN = 4;
    constexpr int TCOLS = C / TN;
    constexpr int NT    = (BM / TM) * TCOLS;    // 256
    constexpr int GW    = (C / 2) / TN;
    __shared__ __align__(16) float Xs[BK][BM];
    __shared__ __align__(16) float Ws[BK][C];
    const int tid = threadIdx.x;
    const int tc = tid % TCOLS, tr = tid / TCOLS;
    const int row0 = blockIdx.x * BM;
    ull acc2[TM / 2][TN];
#pragma unroll
    for (int ip = 0; ip < TM / 2; ip++)
#pragma unroll
        for (int j = 0; j < TN; j++) acc2[ip][j] = pack2(0.f, 0.f);

    for (int kt = 0; kt < K; kt += BK) {
#pragma unroll
        for (int idx = tid; idx < BM * BK / 4; idx += NT) {
            int m = idx / (BK / 4), q = idx % (BK / 4);
            float4 v = make_float4(0.f, 0.f, 0.f, 0.f);
            if (row0 + m < n)
                v = *(const float4*)&X[(long long)(row0 + m) * K + kt + q * 4];
            Xs[q * 4 + 0][m] = v.x; Xs[q * 4 + 1][m] = v.y;
            Xs[q * 4 + 2][m] = v.z; Xs[q * 4 + 3][m] = v.w;
        }
#pragma unroll
        for (int idx = tid; idx < BK * C / 4; idx += NT) {
            int k = idx / (C / 4), q = idx % (C / 4);
            *(float4*)&Ws[k][q * 4] = *(const float4*)&W[(kt + k) * C + q * 4];
        }
        __syncthreads();
#pragma unroll
        for (int k = 0; k < BK; k++) {
            ull x2[TM / 2];
#pragma unroll
            for (int ip = 0; ip < TM / 2; ip++)
                x2[ip] = *(const ull*)&Xs[k][tr * TM + 2 * ip];
            float4 w = *(const float4*)&Ws[k][tc * TN];
            ull wd[TN] = {pack2(w.x, w.x), pack2(w.y, w.y),
                          pack2(w.z, w.z), pack2(w.w, w.w)};
#pragma unroll
            for (int ip = 0; ip < TM / 2; ip++)
#pragma unroll
                for (int j = 0; j < TN; j++)
                    acc2[ip][j] = fma2(x2[ip], wd[j], acc2[ip][j]);
        }
        __syncthreads();
    }
    float accf[TM][TN];
#pragma unroll
    for (int ip = 0; ip < TM / 2; ip++)
#pragma unroll
        for (int j = 0; j < TN; j++)
            unpack2(acc2[ip][j], accf[2 * ip][j], accf[2 * ip + 1][j]);
#pragma unroll
    for (int i = 0; i < TM; i++) {
        int r = row0 + tr * TM + i;
        if (r < n) {
            __half2 h0 = __floats2half2_rn(accf[i][0], accf[i][1]);
            __half2 h1 = __floats2half2_rn(accf[i][2], accf[i][3]);
            uint2 u; u.x = *(unsigned*)&h0; u.y = *(unsigned*)&h1;
            *(uint2*)&Yh[(long long)r * C + tc * TN] = u;
        }
    }
    float4 av = ((const float4*)As)[tc];
    float4 dv = ((const float4*)Ad)[tc];
    float sdot[TM], ddot[TM];
#pragma unroll
    for (int i = 0; i < TM; i++) {
        sdot[i] = accf[i][0] * av.x + accf[i][1] * av.y +
                  accf[i][2] * av.z + accf[i][3] * av.w;
        ddot[i] = accf[i][0] * dv.x + accf[i][1] * dv.y +
                  accf[i][2] * dv.z + accf[i][3] * dv.w;
#pragma unroll
        for (int o = GW / 2; o; o >>= 1) {
            sdot[i] += __shfl_xor_sync(0xffffffffu, sdot[i], o);
            ddot[i] += __shfl_xor_sync(0xffffffffu, ddot[i], o);
        }
    }
    if ((tc & (GW - 1)) == 0) {
        int h = (tc / GW) & 1;
#pragma unroll
        for (int i = 0; i < TM; i++) {
            int r = row0 + tr * TM + i;
            if (r < n) {
                ((float*)g_as)[r * 2 + h] = sdot[i];
                ((float*)g_ad)[r * 2 + h] = ddot[i];
            }
        }
    }
}

// ---- agg1: 2 edges/iteration, 16-lane groups, 8 ch/lane (uint4 gather) -----
__global__ void agg1_k(const __half* __restrict__ xph, const float* __restrict__ b1,
                       float* __restrict__ h, int n) {
    int g = blockIdx.x * blockDim.x + threadIdx.x;
    int node = g >> 5, lane = g & 31;
    if (node >= n) return;
    int sub = lane & 15, grp = lane >> 4;
    int start = g_row[node], deg = g_deg[node];
    float2 ad = g_ad[node];
    float acc[8];
#pragma unroll
    for (int i = 0; i < 8; i++) acc[i] = 0.f;
    float d0 = 0.f, d1 = 0.f;
    const uint4* xp = (const uint4*)xph;

    if (deg <= 32) {                       // fast path (~85% of nodes)
        int s = 0; float p0 = 0.f, p1 = 0.f;
        if (lane < deg) {
            s = g_src[start + lane];
            float2 as = g_as[s];
            float e0 = as.x + ad.x; e0 = e0 > 0.f ? e0 : 0.2f * e0;
            float e1 = as.y + ad.y; e1 = e1 > 0.f ? e1 : 0.2f * e1;
            p0 = __expf(e0); p1 = __expf(e1);
        }
        d0 = p0; d1 = p1;
        for (int j = 0; j < deg; j += 2) {
            int idx = j + grp;
            int   ss = __shfl_sync(0xffffffffu, s,  idx);
            float f0 = __shfl_sync(0xffffffffu, p0, idx);
            float f1 = __shfl_sync(0xffffffffu, p1, idx);
            float a  = (idx < deg) ? (sub < 8 ? f0 : f1) : 0.f;
            uint4 u = xp[ss * 16 + sub];
            float2 va = __half22float2(*(__half2*)&u.x);
            float2 vb = __half22float2(*(__half2*)&u.y);
            float2 vc = __half22float2(*(__half2*)&u.z);
            float2 vd = __half22float2(*(__half2*)&u.w);
            acc[0] = fmaf(va.x, a, acc[0]); acc[1] = fmaf(va.y, a, acc[1]);
            acc[2] = fmaf(vb.x, a, acc[2]); acc[3] = fmaf(vb.y, a, acc[3]);
            acc[4] = fmaf(vc.x, a, acc[4]); acc[5] = fmaf(vc.y, a, acc[5]);
            acc[6] = fmaf(vd.x, a, acc[6]); acc[7] = fmaf(vd.y, a, acc[7]);
        }
    } else {
        for (int base = 0; base < deg; base += 32) {
            int rem = deg - base; if (rem > 32) rem = 32;
            int s = 0; float p0 = 0.f, p1 = 0.f;
            if (lane < rem) {
                s = g_src[start + base + lane];
                float2 as = g_as[s];
                float e0 = as.x + ad.x; e0 = e0 > 0.f ? e0 : 0.2f * e0;
                float e1 = as.y + ad.y; e1 = e1 > 0.f ? e1 : 0.2f * e1;
                p0 = __expf(e0); p1 = __expf(e1);
            }
            d0 += p0; d1 += p1;
            for (int j = 0; j < rem; j += 2) {
                int idx = j + grp;
                int   ss = __shfl_sync(0xffffffffu, s,  idx & 31);
                float f0 = __shfl_sync(0xffffffffu, p0, idx & 31);
                float f1 = __shfl_sync(0xffffffffu, p1, idx & 31);
                float a  = (idx < rem) ? (sub < 8 ? f0 : f1) : 0.f;
                uint4 u = xp[ss * 16 + sub];
                float2 va = __half22float2(*(__half2*)&u.x);
                float2 vb = __half22float2(*(__half2*)&u.y);
                float2 vc = __half22float2(*(__half2*)&u.z);
                float2 vd = __half22float2(*(__half2*)&u.w);
                acc[0] = fmaf(va.x, a, acc[0]); acc[1] = fmaf(va.y, a, acc[1]);
                acc[2] = fmaf(vb.x, a, acc[2]); acc[3] = fmaf(vb.y, a, acc[3]);
                acc[4] = fmaf(vc.x, a, acc[4]); acc[5] = fmaf(vc.y, a, acc[5]);
                acc[6] = fmaf(vd.x, a, acc[6]); acc[7] = fmaf(vd.y, a, acc[7]);
            }
        }
    }
#pragma unroll
    for (int i = 0; i < 8; i++) acc[i] += __shfl_xor_sync(0xffffffffu, acc[i], 16);
#pragma unroll
    for (int o = 16; o; o >>= 1) {
        d0 += __shfl_xor_sync(0xffffffffu, d0, o);
        d1 += __shfl_xor_sync(0xffffffffu, d1, o);
    }
    if (lane < 16) {
        float r = 1.f / (sub < 8 ? d0 : d1);   // channels sub*8..+7: head0 iff sub<8
        float4 b0 = ((const float4*)b1)[sub * 2];
        float4 b1v = ((const float4*)b1)[sub * 2 + 1];
        float o0 = fmaf(acc[0], r, b0.x),  o1 = fmaf(acc[1], r, b0.y);
        float o2 = fmaf(acc[2], r, b0.z),  o3 = fmaf(acc[3], r, b0.w);
        float o4 = fmaf(acc[4], r, b1v.x), o5 = fmaf(acc[5], r, b1v.y);
        float o6 = fmaf(acc[6], r, b1v.z), o7 = fmaf(acc[7], r, b1v.w);
        o0 = o0 > 0.f ? o0 : expm1f(o0); o1 = o1 > 0.f ? o1 : expm1f(o1);
        o2 = o2 > 0.f ? o2 : expm1f(o2); o3 = o3 > 0.f ? o3 : expm1f(o3);
        o4 = o4 > 0.f ? o4 : expm1f(o4); o5 = o5 > 0.f ? o5 : expm1f(o5);
        o6 = o6 > 0.f ? o6 : expm1f(o6); o7 = o7 > 0.f ? o7 : expm1f(o7);
        ((float4*)h)[node * 32 + sub * 2]     = make_float4(o0, o1, o2, o3);
        ((float4*)h)[node * 32 + sub * 2 + 1] = make_float4(o4, o5, o6, o7);
    }
}

// ---- agg2: 2 edges/iteration, 16-lane groups, 4 ch/lane (uint2 gather) -----
__global__ void agg2_k(const __half* __restrict__ xph, const float* __restrict__ b2,
                       float* __restrict__ out, int n) {
    int g = blockIdx.x * blockDim.x + threadIdx.x;
    int node = g >> 5, lane = g & 31;
    if (node >= n) return;
    int sub = lane & 15, grp = lane >> 4;
    int start = g_row[node], deg = g_deg[node];
    float2 ad = g_ad[node];
    float acc[4];
#pragma unroll
    for (int i = 0; i < 4; i++) acc[i] = 0.f;
    float d0 = 0.f, d1 = 0.f;
    const uint2* xp = (const uint2*)xph;

    if (deg <= 32) {
        int s = 0; float p0 = 0.f, p1 = 0.f;
        if (lane < deg) {
            s = g_src[start + lane];
            float2 as = g_as[s];
            float e0 = as.x + ad.x; e0 = e0 > 0.f ? e0 : 0.2f * e0;
            float e1 = as.y + ad.y; e1 = e1 > 0.f ? e1 : 0.2f * e1;
            p0 = __expf(e0); p1 = __expf(e1);
        }
        d0 = p0; d1 = p1;
        for (int j = 0; j < deg; j += 2) {
            int idx = j + grp;
            int   ss = __shfl_sync(0xffffffffu, s,  idx);
            float f0 = __shfl_sync(0xffffffffu, p0, idx);
            float f1 = __shfl_sync(0xffffffffu, p1, idx);
            float a  = (idx < deg) ? (sub < 8 ? f0 : f1) : 0.f;
            uint2 u = xp[ss * 16 + sub];
            float2 va = __half22float2(*(__half2*)&u.x);
            float2 vb = __half22float2(*(__half2*)&u.y);
            acc[0] = fmaf(va.x, a, acc[0]); acc[1] = fmaf(va.y, a, acc[1]);
            acc[2] = fmaf(vb.x, a, acc[2]); acc[3] = fmaf(vb.y, a, acc[3]);
        }
    } else {
        for (int base = 0; base < deg; base += 32) {
            int rem = deg - base; if (rem > 32) rem = 32;
            int s = 0; float p0 = 0.f, p1 = 0.f;
            if (lane < rem) {
                s = g_src[start + base + lane];
                float2 as = g_as[s];
                float e0 = as.x + ad.x; e0 = e0 > 0.f ? e0 : 0.2f * e0;
                float e1 = as.y + ad.y; e1 = e1 > 0.f ? e1 : 0.2f * e1;
                p0 = __expf(e0); p1 = __expf(e1);
            }
            d0 += p0; d1 += p1;
            for (int j = 0; j < rem; j += 2) {
                int idx = j + grp;
                int   ss = __shfl_sync(0xffffffffu, s,  idx & 31);
                float f0 = __shfl_sync(0xffffffffu, p0, idx & 31);
                float f1 = __shfl_sync(0xffffffffu, p1, idx & 31);
                float a  = (idx < rem) ? (sub < 8 ? f0 : f1) : 0.f;
                uint2 u = xp[ss * 16 + sub];
                float2 va = __half22float2(*(__half2*)&u.x);
                float2 vb = __half22float2(*(__half2*)&u.y);
                acc[0] = fmaf(va.x, a, acc[0]); acc[1] = fmaf(va.y, a, acc[1]);
                acc[2] = fmaf(vb.x, a, acc[2]); acc[3] = fmaf(vb.y, a, acc[3]);
            }
        }
    }
#pragma unroll
    for (int i = 0; i < 4; i++) acc[i] += __shfl_xor_sync(0xffffffffu, acc[i], 16);
#pragma unroll
    for (int o = 16; o; o >>= 1) {
        d0 += __shfl_xor_sync(0xffffffffu, d0, o);
        d1 += __shfl_xor_sync(0xffffffffu, d1, o);
    }
    float r = 1.f / (sub < 8 ? d0 : d1);       // channels sub*4..+3: head0 iff sub<8
    float2 c0 = ((const float2*)b2)[sub * 2];
    float2 c1 = ((const float2*)b2)[sub * 2 + 1];
    float v0 = fmaf(acc[0], r, c0.x), v1 = fmaf(acc[1], r, c0.y);
    float v2 = fmaf(acc[2], r, c1.x), v3 = fmaf(acc[3], r, c1.y);
    // log_softmax over 64 channels: both 16-lane groups hold identical folded
    // values, so reduce within the 16-lane group only (offsets 8,4,2,1).
    float m = fmaxf(fmaxf(v0, v1), fmaxf(v2, v3));
#pragma unroll
    for (int o = 8; o; o >>= 1) m = fmaxf(m, __shfl_xor_sync(0xffffffffu, m, o));
    float sm = __expf(v0 - m) + __expf(v1 - m) + __expf(v2 - m) + __expf(v3 - m);
#pragma unroll
    for (int o = 8; o; o >>= 1) sm += __shfl_xor_sync(0xffffffffu, sm, o);
    float lse = m + __logf(sm);
    if (lane < 16)
        ((float4*)out)[node * 16 + sub] =
            make_float4(v0 - lse, v1 - lse, v2 - lse, v3 - lse);
}

// ---------------------------------------------------------------------------
extern "C" void kernel_launch(void* const* d_in, const int* in_sizes, int n_in,
                              void* d_out, int out_size) {
    const float* x   = (const float*)d_in[0];
    const void*  ei  = d_in[1];
    const float* W1  = (const float*)d_in[2];
    const float* a1s = (const float*)d_in[3];
    const float* a1d = (const float*)d_in[4];
    const float* b1  = (const float*)d_in[5];
    const float* W2  = (const float*)d_in[6];
    const float* a2s = (const float*)d_in[7];
    const float* a2d = (const float*)d_in[8];
    const float* b2  = (const float*)d_in[9];
    float* out = (float*)d_out;

    const int n  = in_sizes[0] / 128;          // 50000
    const int E  = in_sizes[1] / 2;            // 800000
    const int Et = E + n;
    const int nb = (n + 1023) / 1024;

    __half *xp1h, *xp2h; float *h; int *degp;
    cudaGetSymbolAddress((void**)&xp1h, g_xp1h);
    cudaGetSymbolAddress((void**)&h,    g_h);
    cudaGetSymbolAddress((void**)&xp2h, g_xp2h);
    cudaGetSymbolAddress((void**)&degp, g_deg);

    // one-time host-side resources (no device memory involved)
    static cudaStream_t s_csr = 0;
    static cudaEvent_t  ev_fork = 0, ev_join = 0;
    if (s_csr == 0) {
        cudaStreamCreateWithFlags(&s_csr, cudaStreamNonBlocking);
        cudaEventCreateWithFlags(&ev_fork, cudaEventDisableTiming);
        cudaEventCreateWithFlags(&ev_join, cudaEventDisableTiming);
    }

    const int B = 256;
    const int nwB = (n * 32 + B - 1) / B;

    bool fork = (s_csr != 0 && ev_fork != 0 && ev_join != 0);
    cudaStream_t sc = fork ? s_csr : 0;

    // detect runs on the MAIN stream before the fork (hist needs g_is32)
    detect_k<<<16, 256>>>((const unsigned*)ei);

    if (fork) {
        cudaEventRecord(ev_fork, 0);
        cudaStreamWaitEvent(sc, ev_fork, 0);
    }

    // ---- CSR build (side stream) ----
    cudaMemsetAsync(degp, 0, n * sizeof(int), sc);   // zero g_deg (memset node)
    hist_k   <<<(Et + B - 1) / B, B, 0, sc>>>(ei, E, n);
    scan_k   <<<nb, 256, 0, sc>>>(n);
    scatter_k<<<(Et + B - 1) / B, B, 0, sc>>>(ei, E, n);

    // ---- layer-1 GEMM (+attn dots), concurrent with CSR build ----
    gemm_attn_k<128, 64><<<(n + 63) / 64, 256>>>(x, W1, xp1h, a1s, a1d, n);

    if (fork) {
        cudaEventRecord(ev_join, sc);
        cudaStreamWaitEvent(0, ev_join, 0);
    }

    agg1_k<<<nwB, B>>>(xp1h, b1, h, n);

    // ---- layer 2 ----
    gemm_attn_k<64, 128><<<(n + 127) / 128, 256>>>(h, W2, xp2h, a2s, a2d, n);
    agg2_k<<<nwB, B>>>(xp2h, b2, out, n);
}

// round 17
// speedup vs baseline: 1.0640x; 1.0254x over previous
#include <cuda_runtime.h>
#include <cuda_fp16.h>
#include <math.h>

// ---------------------------------------------------------------------------
// 2-layer GAT forward, CSR-based, forked graph capture.  (R16 structure)
//   main: detect -> [fork] gemm1 (+attn dots)
//   side: memset(g_deg) / hist(+slot) / fused scan / scatter
//   join -> agg1 -> gemm2(+attn) -> agg2
// Flat softmax via __expf.  Agg: 2 edges/warp-iter via 16-lane groups,
// fp16 HFMA2 accumulation (fp32 denominators + epilogue).
// ---------------------------------------------------------------------------

#define NN 50000
#define EE 800000
#define ET (EE + NN)
#define NB ((NN + 1023) / 1024)

typedef unsigned long long ull;

// -------- scratch (device globals; no allocation allowed) -------------------
__device__ __half g_xp1h[NN * 128];
__device__ float  g_h   [NN * 128];
__device__ __half g_xp2h[NN * 64];
__device__ float2 g_as  [NN];
__device__ float2 g_ad  [NN];
__device__ int    g_deg[NN];
__device__ int    g_row[NN];
__device__ int    g_src[ET];
__device__ int    g_slot[ET];
__device__ int    g_is32 = 0;   // only ever set to 1 (idempotent across replays)

// -------- packed f32x2 helpers ----------------------------------------------
__device__ __forceinline__ ull pack2(float lo, float hi) {
    ull r; asm("mov.b64 %0, {%1, %2};" : "=l"(r) : "f"(lo), "f"(hi)); return r;
}
__device__ __forceinline__ void unpack2(ull v, float& lo, float& hi) {
    asm("mov.b64 {%0, %1}, %2;" : "=f"(lo), "=f"(hi) : "l"(v));
}
__device__ __forceinline__ ull fma2(ull a, ull b, ull c) {
    ull d; asm("fma.rn.f32x2 %0, %1, %2, %3;" : "=l"(d) : "l"(a), "l"(b), "l"(c));
    return d;
}

// -------- edge decode --------------------------------------------------------
__device__ __forceinline__ void load_edge(const void* ei, int E, int e,
                                          int& s, int& d) {
    if (e >= E) { s = d = e - E; return; }            // self loop
    if (g_is32) {
        const int* p = (const int*)ei;
        s = p[e]; d = p[E + e];
    } else {
        const long long* p = (const long long*)ei;
        s = (int)p[e]; d = (int)p[E + e];
    }
}

// -------- CSR build ----------------------------------------------------------
// int32 layout => odd 32-bit words are node ids (some nonzero);
// int64 layout => odd words are high halves of values < 2^31 => all zero.
__global__ void detect_k(const unsigned* w) {
    int i = blockIdx.x * blockDim.x + threadIdx.x;
    if (i < 4096 && w[2 * i + 1] != 0u) g_is32 = 1;
}
// histogram + per-edge slot (atomicAdd return value); g_deg pre-zeroed by memset
__global__ void hist_k(const void* ei, int E, int n) {
    int e = blockIdx.x * blockDim.x + threadIdx.x;
    if (e >= E + n) return;
    int d;
    if (e >= E) d = e - E;
    else if (g_is32) d = ((const int*)ei)[E + e];
    else             d = (int)((const long long*)ei)[E + e];
    g_slot[e] = atomicAdd(&g_deg[d], 1);
}
// fused device-wide exclusive scan of g_deg -> g_row.
__global__ void scan_k(int n) {
    __shared__ int wsum[8], woff[8], blkoff_s;
    int b = blockIdx.x, t = threadIdx.x;
    int lane = t & 31, w = t >> 5;
    int pre = 0;
    for (int i = t; i < b * 1024; i += 256) pre += g_deg[i];
#pragma unroll
    for (int o = 16; o; o >>= 1) pre += __shfl_xor_sync(0xffffffffu, pre, o);
    if (lane == 0) wsum[w] = pre;
    __syncthreads();
    if (t == 0) {
        int tot = 0;
#pragma unroll
        for (int j = 0; j < 8; j++) tot += wsum[j];
        blkoff_s = tot;
    }
    __syncthreads();
    int blkoff = blkoff_s;
    int base = b * 1024 + t * 4;
    int v[4];
#pragma unroll
    for (int j = 0; j < 4; j++) {
        int i = base + j;
        v[j] = (i < n) ? g_deg[i] : 0;
    }
    int s = v[0] + v[1] + v[2] + v[3];
    int inc = s;
#pragma unroll
    for (int o = 1; o < 32; o <<= 1) {
        int x = __shfl_up_sync(0xffffffffu, inc, o);
        if (lane >= o) inc += x;
    }
    if (lane == 31) wsum[w] = inc;
    __syncthreads();
    if (w == 0) {
        int x = (lane < 8) ? wsum[lane] : 0;
        int i8 = x;
#pragma unroll
        for (int o = 1; o < 8; o <<= 1) {
            int y = __shfl_up_sync(0xffffffffu, i8, o);
            if (lane >= o) i8 += y;
        }
        if (lane < 8) woff[lane] = i8 - x;
    }
    __syncthreads();
    int off = blkoff + woff[w] + (inc - s);
#pragma unroll
    for (int j = 0; j < 4; j++) {
        int i = base + j;
        if (i < n) g_row[i] = off;
        off += v[j];
    }
}
// atomic-free scatter: slot precomputed in hist
__global__ void scatter_k(const void* ei, int E, int n) {
    int e = blockIdx.x * blockDim.x + threadIdx.x;
    if (e >= E + n) return;
    int s, d; load_edge(ei, E, e, s, d);
    g_src[g_row[d] + g_slot[e]] = s;
}

// -------- f32x2 GEMM + fused attn dots; fp16 output -------------------------
template <int C, int BM>
__global__ void gemm_attn_k(const float* __restrict__ X, const float* __restrict__ W,
                            __half* __restrict__ Yh, const float* __restrict__ As,
                            const float* __restrict__ Ad, int n) {
    constexpr int K = 128, BK = 16, TM = 8, TN = 4;
    constexpr int TCOLS = C / TN;
    constexpr int NT    = (BM / TM) * TCOLS;    // 256
    constexpr int GW    = (C / 2) / TN;
    __shared__ __align__(16) float Xs[BK][BM];
    __shared__ __align__(16) float Ws[BK][C];
    const int tid = threadIdx.x;
    const int tc = tid % TCOLS, tr = tid / TCOLS;
    const int row0 = blockIdx.x * BM;
    ull acc2[TM / 2][TN];
#pragma unroll
    for (int ip = 0; ip < TM / 2; ip++)
#pragma unroll
        for (int j = 0; j < TN; j++) acc2[ip][j] = pack2(0.f, 0.f);

    for (int kt = 0; kt < K; kt += BK) {
#pragma unroll
        for (int idx = tid; idx < BM * BK / 4; idx += NT) {
            int m = idx / (BK / 4), q = idx % (BK / 4);
            float4 v = make_float4(0.f, 0.f, 0.f, 0.f);
            if (row0 + m < n)
                v = *(const float4*)&X[(long long)(row0 + m) * K + kt + q * 4];
            Xs[q * 4 + 0][m] = v.x; Xs[q * 4 + 1][m] = v.y;
            Xs[q * 4 + 2][m] = v.z; Xs[q * 4 + 3][m] = v.w;
        }
#pragma unroll
        for (int idx = tid; idx < BK * C / 4; idx += NT) {
            int k = idx / (C / 4), q = idx % (C / 4);
            *(float4*)&Ws[k][q * 4] = *(const float4*)&W[(kt + k) * C + q * 4];
        }
        __syncthreads();
#pragma unroll
        for (int k = 0; k < BK; k++) {
            ull x2[TM / 2];
#pragma unroll
            for (int ip = 0; ip < TM / 2; ip++)
                x2[ip] = *(const ull*)&Xs[k][tr * TM + 2 * ip];
            float4 w = *(const float4*)&Ws[k][tc * TN];
            ull wd[TN] = {pack2(w.x, w.x), pack2(w.y, w.y),
                          pack2(w.z, w.z), pack2(w.w, w.w)};
#pragma unroll
            for (int ip = 0; ip < TM / 2; ip++)
#pragma unroll
                for (int j = 0; j < TN; j++)
                    acc2[ip][j] = fma2(x2[ip], wd[j], acc2[ip][j]);
        }
        __syncthreads();
    }
    float accf[TM][TN];
#pragma unroll
    for (int ip = 0; ip < TM / 2; ip++)
#pragma unroll
        for (int j = 0; j < TN; j++)
            unpack2(acc2[ip][j], accf[2 * ip][j], accf[2 * ip + 1][j]);
#pragma unroll
    for (int i = 0; i < TM; i++) {
        int r = row0 + tr * TM + i;
        if (r < n) {
            __half2 h0 = __floats2half2_rn(accf[i][0], accf[i][1]);
            __half2 h1 = __floats2half2_rn(accf[i][2], accf[i][3]);
            uint2 u; u.x = *(unsigned*)&h0; u.y = *(unsigned*)&h1;
            *(uint2*)&Yh[(long long)r * C + tc * TN] = u;
        }
    }
    float4 av = ((const float4*)As)[tc];
    float4 dv = ((const float4*)Ad)[tc];
    float sdot[TM], ddot[TM];
#pragma unroll
    for (int i = 0; i < TM; i++) {
        sdot[i] = accf[i][0] * av.x + accf[i][1] * av.y +
                  accf[i][2] * av.z + accf[i][3] * av.w;
        ddot[i] = accf[i][0] * dv.x + accf[i][1] * dv.y +
                  accf[i][2] * dv.z + accf[i][3] * dv.w;
#pragma unroll
        for (int o = GW / 2; o; o >>= 1) {
            sdot[i] += __shfl_xor_sync(0xffffffffu, sdot[i], o);
            ddot[i] += __shfl_xor_sync(0xffffffffu, ddot[i], o);
        }
    }
    if ((tc & (GW - 1)) == 0) {
        int h = (tc / GW) & 1;
#pragma unroll
        for (int i = 0; i < TM; i++) {
            int r = row0 + tr * TM + i;
            if (r < n) {
                ((float*)g_as)[r * 2 + h] = sdot[i];
                ((float*)g_ad)[r * 2 + h] = ddot[i];
            }
        }
    }
}

// ---- agg1: 2 edges/iter, 16-lane groups, HFMA2 fp16 accumulation -----------
__global__ void agg1_k(const __half* __restrict__ xph, const float* __restrict__ b1,
                       float* __restrict__ h, int n) {
    int g = blockIdx.x * blockDim.x + threadIdx.x;
    int node = g >> 5, lane = g & 31;
    if (node >= n) return;
    int sub = lane & 15, grp = lane >> 4;
    int start = g_row[node], deg = g_deg[node];
    float2 ad = g_ad[node];
    __half2 acch[4];
#pragma unroll
    for (int i = 0; i < 4; i++) acch[i] = __float2half2_rn(0.f);
    float d0 = 0.f, d1 = 0.f;
    const uint4* xp = (const uint4*)xph;

    if (deg <= 32) {                       // fast path (~85% of nodes)
        int s = 0; float p0 = 0.f, p1 = 0.f;
        if (lane < deg) {
            s = g_src[start + lane];
            float2 as = g_as[s];
            float e0 = as.x + ad.x; e0 = e0 > 0.f ? e0 : 0.2f * e0;
            float e1 = as.y + ad.y; e1 = e1 > 0.f ? e1 : 0.2f * e1;
            p0 = __expf(e0); p1 = __expf(e1);
        }
        d0 = p0; d1 = p1;
        for (int j = 0; j < deg; j += 2) {
            int idx = j + grp;
            int   ss = __shfl_sync(0xffffffffu, s,  idx);
            float f0 = __shfl_sync(0xffffffffu, p0, idx);
            float f1 = __shfl_sync(0xffffffffu, p1, idx);
            float a  = (idx < deg) ? (sub < 8 ? f0 : f1) : 0.f;
            __half2 a2 = __float2half2_rn(a);
            uint4 u = xp[ss * 16 + sub];
            acch[0] = __hfma2(*(__half2*)&u.x, a2, acch[0]);
            acch[1] = __hfma2(*(__half2*)&u.y, a2, acch[1]);
            acch[2] = __hfma2(*(__half2*)&u.z, a2, acch[2]);
            acch[3] = __hfma2(*(__half2*)&u.w, a2, acch[3]);
        }
    } else {
        for (int base = 0; base < deg; base += 32) {
            int rem = deg - base; if (rem > 32) rem = 32;
            int s = 0; float p0 = 0.f, p1 = 0.f;
            if (lane < rem) {
                s = g_src[start + base + lane];
                float2 as = g_as[s];
                float e0 = as.x + ad.x; e0 = e0 > 0.f ? e0 : 0.2f * e0;
                float e1 = as.y + ad.y; e1 = e1 > 0.f ? e1 : 0.2f * e1;
                p0 = __expf(e0); p1 = __expf(e1);
            }
            d0 += p0; d1 += p1;
            for (int j = 0; j < rem; j += 2) {
                int idx = j + grp;
                int   ss = __shfl_sync(0xffffffffu, s,  idx & 31);
                float f0 = __shfl_sync(0xffffffffu, p0, idx & 31);
                float f1 = __shfl_sync(0xffffffffu, p1, idx & 31);
                float a  = (idx < rem) ? (sub < 8 ? f0 : f1) : 0.f;
                __half2 a2 = __float2half2_rn(a);
                uint4 u = xp[ss * 16 + sub];
                acch[0] = __hfma2(*(__half2*)&u.x, a2, acch[0]);
                acch[1] = __hfma2(*(__half2*)&u.y, a2, acch[1]);
                acch[2] = __hfma2(*(__half2*)&u.z, a2, acch[2]);
                acch[3] = __hfma2(*(__half2*)&u.w, a2, acch[3]);
            }
        }
    }
    // widen to fp32, fold the two 16-lane groups
    float acc[8];
#pragma unroll
    for (int i = 0; i < 4; i++) {
        float2 f = __half22float2(acch[i]);
        acc[2 * i] = f.x; acc[2 * i + 1] = f.y;
    }
#pragma unroll
    for (int i = 0; i < 8; i++) acc[i] += __shfl_xor_sync(0xffffffffu, acc[i], 16);
#pragma unroll
    for (int o = 16; o; o >>= 1) {
        d0 += __shfl_xor_sync(0xffffffffu, d0, o);
        d1 += __shfl_xor_sync(0xffffffffu, d1, o);
    }
    if (lane < 16) {
        float r = 1.f / (sub < 8 ? d0 : d1);   // channels sub*8..+7: head0 iff sub<8
        float4 b0 = ((const float4*)b1)[sub * 2];
        float4 b1v = ((const float4*)b1)[sub * 2 + 1];
        float o0 = fmaf(acc[0], r, b0.x),  o1 = fmaf(acc[1], r, b0.y);
        float o2 = fmaf(acc[2], r, b0.z),  o3 = fmaf(acc[3], r, b0.w);
        float o4 = fmaf(acc[4], r, b1v.x), o5 = fmaf(acc[5], r, b1v.y);
        float o6 = fmaf(acc[6], r, b1v.z), o7 = fmaf(acc[7], r, b1v.w);
        o0 = o0 > 0.f ? o0 : expm1f(o0); o1 = o1 > 0.f ? o1 : expm1f(o1);
        o2 = o2 > 0.f ? o2 : expm1f(o2); o3 = o3 > 0.f ? o3 : expm1f(o3);
        o4 = o4 > 0.f ? o4 : expm1f(o4); o5 = o5 > 0.f ? o5 : expm1f(o5);
        o6 = o6 > 0.f ? o6 : expm1f(o6); o7 = o7 > 0.f ? o7 : expm1f(o7);
        ((float4*)h)[node * 32 + sub * 2]     = make_float4(o0, o1, o2, o3);
        ((float4*)h)[node * 32 + sub * 2 + 1] = make_float4(o4, o5, o6, o7);
    }
}

// ---- agg2: 2 edges/iter, 16-lane groups, HFMA2 accumulation, log_softmax ---
__global__ void agg2_k(const __half* __restrict__ xph, const float* __restrict__ b2,
                       float* __restrict__ out, int n) {
    int g = blockIdx.x * blockDim.x + threadIdx.x;
    int node = g >> 5, lane = g & 31;
    if (node >= n) return;
    int sub = lane & 15, grp = lane >> 4;
    int start = g_row[node], deg = g_deg[node];
    float2 ad = g_ad[node];
    __half2 acch[2];
    acch[0] = __float2half2_rn(0.f); acch[1] = __float2half2_rn(0.f);
    float d0 = 0.f, d1 = 0.f;
    const uint2* xp = (const uint2*)xph;

    if (deg <= 32) {
        int s = 0; float p0 = 0.f, p1 = 0.f;
        if (lane < deg) {
            s = g_src[start + lane];
            float2 as = g_as[s];
            float e0 = as.x + ad.x; e0 = e0 > 0.f ? e0 : 0.2f * e0;
            float e1 = as.y + ad.y; e1 = e1 > 0.f ? e1 : 0.2f * e1;
            p0 = __expf(e0); p1 = __expf(e1);
        }
        d0 = p0; d1 = p1;
        for (int j = 0; j < deg; j += 2) {
            int idx = j + grp;
            int   ss = __shfl_sync(0xffffffffu, s,  idx);
            float f0 = __shfl_sync(0xffffffffu, p0, idx);
            float f1 = __shfl_sync(0xffffffffu, p1, idx);
            float a  = (idx < deg) ? (sub < 8 ? f0 : f1) : 0.f;
            __half2 a2 = __float2half2_rn(a);
            uint2 u = xp[ss * 16 + sub];
            acch[0] = __hfma2(*(__half2*)&u.x, a2, acch[0]);
            acch[1] = __hfma2(*(__half2*)&u.y, a2, acch[1]);
        }
    } else {
        for (int base = 0; base < deg; base += 32) {
            int rem = deg - base; if (rem > 32) rem = 32;
            int s = 0; float p0 = 0.f, p1 = 0.f;
            if (lane < rem) {
                s = g_src[start + base + lane];
                float2 as = g_as[s];
                float e0 = as.x + ad.x; e0 = e0 > 0.f ? e0 : 0.2f * e0;
                float e1 = as.y + ad.y; e1 = e1 > 0.f ? e1 : 0.2f * e1;
                p0 = __expf(e0); p1 = __expf(e1);
            }
            d0 += p0; d1 += p1;
            for (int j = 0; j < rem; j += 2) {
                int idx = j + grp;
                int   ss = __shfl_sync(0xffffffffu, s,  idx & 31);
                float f0 = __shfl_sync(0xffffffffu, p0, idx & 31);
                float f1 = __shfl_sync(0xffffffffu, p1, idx & 31);
                float a  = (idx < rem) ? (sub < 8 ? f0 : f1) : 0.f;
                __half2 a2 = __float2half2_rn(a);
                uint2 u = xp[ss * 16 + sub];
                acch[0] = __hfma2(*(__half2*)&u.x, a2, acch[0]);
                acch[1] = __hfma2(*(__half2*)&u.y, a2, acch[1]);
            }
        }
    }
    float acc[4];
    {
        float2 f0v = __half22float2(acch[0]);
        float2 f1v = __half22float2(acch[1]);
        acc[0] = f0v.x; acc[1] = f0v.y; acc[2] = f1v.x; acc[3] = f1v.y;
    }
#pragma unroll
    for (int i = 0; i < 4; i++) acc[i] += __shfl_xor_sync(0xffffffffu, acc[i], 16);
#pragma unroll
    for (int o = 16; o; o >>= 1) {
        d0 += __shfl_xor_sync(0xffffffffu, d0, o);
        d1 += __shfl_xor_sync(0xffffffffu, d1, o);
    }
    float r = 1.f / (sub < 8 ? d0 : d1);       // channels sub*4..+3: head0 iff sub<8
    float2 c0 = ((const float2*)b2)[sub * 2];
    float2 c1 = ((const float2*)b2)[sub * 2 + 1];
    float v0 = fmaf(acc[0], r, c0.x), v1 = fmaf(acc[1], r, c0.y);
    float v2 = fmaf(acc[2], r, c1.x), v3 = fmaf(acc[3], r, c1.y);
    float m = fmaxf(fmaxf(v0, v1), fmaxf(v2, v3));
#pragma unroll
    for (int o = 8; o; o >>= 1) m = fmaxf(m, __shfl_xor_sync(0xffffffffu, m, o));
    float sm = __expf(v0 - m) + __expf(v1 - m) + __expf(v2 - m) + __expf(v3 - m);
#pragma unroll
    for (int o = 8; o; o >>= 1) sm += __shfl_xor_sync(0xffffffffu, sm, o);
    float lse = m + __logf(sm);
    if (lane < 16)
        ((float4*)out)[node * 16 + sub] =
            make_float4(v0 - lse, v1 - lse, v2 - lse, v3 - lse);
}

// ---------------------------------------------------------------------------
extern "C" void kernel_launch(void* const* d_in, const int* in_sizes, int n_in,
                              void* d_out, int out_size) {
    const float* x   = (const float*)d_in[0];
    const void*  ei  = d_in[1];
    const float* W1  = (const float*)d_in[2];
    const float* a1s = (const float*)d_in[3];
    const float* a1d = (const float*)d_in[4];
    const float* b1  = (const float*)d_in[5];
    const float* W2  = (const float*)d_in[6];
    const float* a2s = (const float*)d_in[7];
    const float* a2d = (const float*)d_in[8];
    const float* b2  = (const float*)d_in[9];
    float* out = (float*)d_out;

    const int n  = in_sizes[0] / 128;          // 50000
    const int E  = in_sizes[1] / 2;            // 800000
    const int Et = E + n;
    const int nb = (n + 1023) / 1024;

    __half *xp1h, *xp2h; float *h; int *degp;
    cudaGetSymbolAddress((void**)&xp1h, g_xp1h);
    cudaGetSymbolAddress((void**)&h,    g_h);
    cudaGetSymbolAddress((void**)&xp2h, g_xp2h);
    cudaGetSymbolAddress((void**)&degp, g_deg);

    // one-time host-side resources (no device memory involved)
    static cudaStream_t s_csr = 0;
    static cudaEvent_t  ev_fork = 0, ev_join = 0;
    if (s_csr == 0) {
        cudaStreamCreateWithFlags(&s_csr, cudaStreamNonBlocking);
        cudaEventCreateWithFlags(&ev_fork, cudaEventDisableTiming);
        cudaEventCreateWithFlags(&ev_join, cudaEventDisableTiming);
    }

    const int B = 256;
    const int nwB = (n * 32 + B - 1) / B;

    bool fork = (s_csr != 0 && ev_fork != 0 && ev_join != 0);
    cudaStream_t sc = fork ? s_csr : 0;

    // detect runs on the MAIN stream before the fork (hist needs g_is32)
    detect_k<<<16, 256>>>((const unsigned*)ei);

    if (fork) {
        cudaEventRecord(ev_fork, 0);
        cudaStreamWaitEvent(sc, ev_fork, 0);
    }

    // ---- CSR build (side stream) ----
    cudaMemsetAsync(degp, 0, n * sizeof(int), sc);   // zero g_deg (memset node)
    hist_k   <<<(Et + B - 1) / B, B, 0, sc>>>(ei, E, n);
    scan_k   <<<nb, 256, 0, sc>>>(n);
    scatter_k<<<(Et + B - 1) / B, B, 0, sc>>>(ei, E, n);

    // ---- layer-1 GEMM (+attn dots), concurrent with CSR build ----
    gemm_attn_k<128, 64><<<(n + 63) / 64, 256>>>(x, W1, xp1h, a1s, a1d, n);

    if (fork) {
        cudaEventRecord(ev_join, sc);
        cudaStreamWaitEvent(0, ev_join, 0);
    }

    agg1_k<<<nwB, B>>>(xp1h, b1, h, n);

    // ---- layer 2 ----
    gemm_attn_k<64, 128><<<(n + 127) / 128, 256>>>(h, W2, xp2h, a2s, a2d, n);
    agg2_k<<<nwB, B>>>(xp2h, b2, out, n);
}